// round 14
// baseline (speedup 1.0000x reference)
#include <cuda_runtime.h>
#include <cuda_bf16.h>
#include <math.h>

#define Bsz 64
#define Tsz 2048
#define Dsz 128
#define NSUB 3
#define WCOLS 768

__device__ float g_Wcat[Dsz * WCOLS];
// TRANSPOSED layout: [b][g][t]  (t contiguous) -> chain threads stream linearly
__device__ float g_gxpx[(size_t)Bsz * WCOLS * Tsz];
__device__ float g_subo[(size_t)Tsz * NSUB * Bsz * 128];  // [t][n][b][o]
__device__ float g_obuf[(size_t)Tsz * Bsz * 128];         // [t][b][u]

__device__ __forceinline__ float2 ffma2(float2 a, float2 b, float2 c) {
    union U { float2 f2; unsigned long long u; };
    U ua, ub, uc, ud;
    ua.f2 = a; ub.f2 = b; uc.f2 = c;
    asm("fma.rn.f32x2 %0, %1, %2, %3;"
        : "=l"(ud.u) : "l"(ua.u), "l"(ub.u), "l"(uc.u));
    return ud.f2;
}

__device__ __forceinline__ float sigmoidf_(float x) {
    return 1.0f / (1.0f + __expf(-x));
}

// concat kernel(128x384) and sub_kernel_x(3,128,128) -> Wcat(128x768)
__global__ void prep_wcat_kernel(const float* __restrict__ kern,
                                 const float* __restrict__ skx) {
    int idx = blockIdx.x * 256 + threadIdx.x;
    if (idx >= Dsz * WCOLS) return;
    int d = idx / WCOLS, g = idx - d * WCOLS;
    float v;
    if (g < 384) v = kern[d * 384 + g];
    else {
        int q = g - 384;
        v = skx[(q >> 7) * (Dsz * 128) + d * 128 + (q & 127)];
    }
    g_Wcat[idx] = v;
}

// Tiled fp32 GEMM: 128x128 tile, BK=32, 256 threads, 8x8 micro via f32x2.
// TRANS=true: write C transposed as [b][g][t] (phase0); else row-major.
template <bool TRANS>
__device__ __forceinline__ void gemm_body(
    const float* __restrict__ A, const float* __restrict__ B,
    float* __restrict__ C, int N, int K,
    const float* __restrict__ bias, bool act)
{
    __shared__ __align__(16) float As[32][132];
    __shared__ __align__(16) float Bs[32][128];
    const int tid = threadIdx.x;
    const int tx = tid & 15, ty = tid >> 4;
    const int m0 = blockIdx.x * 128, n0 = blockIdx.y * 128;

    float2 acc[8][4];
#pragma unroll
    for (int i = 0; i < 8; ++i)
#pragma unroll
        for (int j = 0; j < 4; ++j) acc[i][j] = make_float2(0.f, 0.f);

    const int aR = tid >> 3, aC = (tid & 7) * 4;
    const int bR = tid >> 5, bC = (tid & 31) * 4;

    for (int k0 = 0; k0 < K; k0 += 32) {
#pragma unroll
        for (int r = 0; r < 4; ++r) {
            float4 v = *(const float4*)(A + (size_t)(m0 + r * 32 + aR) * K + (k0 + aC));
            As[aC + 0][r * 32 + aR] = v.x;
            As[aC + 1][r * 32 + aR] = v.y;
            As[aC + 2][r * 32 + aR] = v.z;
            As[aC + 3][r * 32 + aR] = v.w;
        }
#pragma unroll
        for (int r = 0; r < 4; ++r)
            *(float4*)&Bs[r * 8 + bR][bC] =
                *(const float4*)(B + (size_t)(k0 + r * 8 + bR) * N + (n0 + bC));
        __syncthreads();
#pragma unroll
        for (int kk = 0; kk < 32; ++kk) {
            float4 a0 = *(const float4*)&As[kk][ty * 8];
            float4 a1 = *(const float4*)&As[kk][ty * 8 + 4];
            float4 b0 = *(const float4*)&Bs[kk][tx * 8];
            float4 b1 = *(const float4*)&Bs[kk][tx * 8 + 4];
            float2 bb[4] = { make_float2(b0.x, b0.y), make_float2(b0.z, b0.w),
                             make_float2(b1.x, b1.y), make_float2(b1.z, b1.w) };
            float av[8] = { a0.x, a0.y, a0.z, a0.w, a1.x, a1.y, a1.z, a1.w };
#pragma unroll
            for (int i = 0; i < 8; ++i) {
                float2 ad = make_float2(av[i], av[i]);
#pragma unroll
                for (int j = 0; j < 4; ++j)
                    acc[i][j] = ffma2(ad, bb[j], acc[i][j]);
            }
        }
        __syncthreads();
    }

    if (TRANS) {
        // C layout [b][g][t]: tile rows m = b*Tsz + t (single b per tile).
        const int bb_ = m0 / Tsz;
        const int t0 = m0 - bb_ * Tsz;
        float* base = C + (size_t)bb_ * WCOLS * Tsz + t0 + ty * 8;
#pragma unroll
        for (int j = 0; j < 8; ++j) {
            const int g = n0 + tx * 8 + j;
            float o0 = (j & 1) ? acc[0][j >> 1].y : acc[0][j >> 1].x;
            float o1 = (j & 1) ? acc[1][j >> 1].y : acc[1][j >> 1].x;
            float o2 = (j & 1) ? acc[2][j >> 1].y : acc[2][j >> 1].x;
            float o3 = (j & 1) ? acc[3][j >> 1].y : acc[3][j >> 1].x;
            float o4 = (j & 1) ? acc[4][j >> 1].y : acc[4][j >> 1].x;
            float o5 = (j & 1) ? acc[5][j >> 1].y : acc[5][j >> 1].x;
            float o6 = (j & 1) ? acc[6][j >> 1].y : acc[6][j >> 1].x;
            float o7 = (j & 1) ? acc[7][j >> 1].y : acc[7][j >> 1].x;
            *(float4*)(base + (size_t)g * Tsz)     = make_float4(o0, o1, o2, o3);
            *(float4*)(base + (size_t)g * Tsz + 4) = make_float4(o4, o5, o6, o7);
        }
    } else {
        float bvals[8];
#pragma unroll
        for (int j = 0; j < 8; ++j)
            bvals[j] = bias ? bias[n0 + tx * 8 + j] : 0.f;
#pragma unroll
        for (int i = 0; i < 8; ++i) {
            int m = m0 + ty * 8 + i;
            float o[8];
#pragma unroll
            for (int j = 0; j < 4; ++j) {
                o[2 * j + 0] = acc[i][j].x + bvals[2 * j + 0];
                o[2 * j + 1] = acc[i][j].y + bvals[2 * j + 1];
            }
            if (act) {
#pragma unroll
                for (int j = 0; j < 8; ++j) o[j] = sigmoidf_(o[j]);
            }
            *(float4*)&C[(size_t)m * N + n0 + tx * 8]     = make_float4(o[0], o[1], o[2], o[3]);
            *(float4*)&C[(size_t)m * N + n0 + tx * 8 + 4] = make_float4(o[4], o[5], o[6], o[7]);
        }
    }
}

__global__ void __launch_bounds__(256) gemm_phase0_kernel(const float* __restrict__ x) {
    gemm_body<true>(x, g_Wcat, g_gxpx, WCOLS, Dsz, nullptr, false);
}

__global__ void __launch_bounds__(256) gemm_phase2_kernel(const float* __restrict__ aggw,
                                                          const float* __restrict__ aggb) {
    gemm_body<false>(g_subo, aggw, g_obuf, 128, NSUB * 128, aggb, true);
}

// Phase 1: s-chain. blk: n = blk/32, batch pair b0 = (blk%32)*2.
// 256 threads: out = tid>>1 (0..127), kh = tid&1.
__global__ void __launch_bounds__(256, 1) chain_s_kernel(
    const float* __restrict__ skh,   // (3,128,128) [n][o][i]
    const float* __restrict__ dw,    // (3,128,128) [n][i][o']
    const float* __restrict__ db,    // (3,128)
    const float* __restrict__ stk)   // (3,256) [rh|rx]
{
    const int n  = blockIdx.x >> 5;
    const int b0 = (blockIdx.x & 31) * 2;
    const int tid = threadIdx.x;
    const int out = tid >> 1, kh = tid & 1;

    __shared__ __align__(16) float s_s[2][128];
    __shared__ __align__(16) float s_y[2][128];

    const float* skh_n = skh + n * 16384;
    const float* dw_n  = dw  + n * 16384;

    float2 w1[32], w2[32];
#pragma unroll
    for (int i = 0; i < 32; ++i) {
        int k = kh * 64 + 2 * i;
        w1[i] = make_float2(skh_n[k * 128 + out], skh_n[(k + 1) * 128 + out]);
        w2[i] = make_float2(dw_n [k * 128 + out], dw_n [(k + 1) * 128 + out]);
    }
    const float dbv = db[n * 128 + out];
    const float rhv = stk[n * 256 + out];
    const float rxv = stk[n * 256 + 128 + out];

    // streaming px pointers: [b][g][t] layout, t contiguous per thread
    const int gcol = 384 + n * 128 + out;
    const float* px0p = g_gxpx + ((size_t)(b0)     * WCOLS + gcol) * Tsz;
    const float* px1p = g_gxpx + ((size_t)(b0 + 1) * WCOLS + gcol) * Tsz;
    float* so0p = g_subo + n * (Bsz * 128) + (b0)     * 128 + out;
    float* so1p = g_subo + n * (Bsz * 128) + (b0 + 1) * 128 + out;

    if (tid < 128) { s_s[0][tid] = 0.f; s_s[1][tid] = 0.f; }

    float pxa0 = 0.f, pxa1 = 0.f, pxa2 = 0.f;
    float pxb0 = 0.f, pxb1 = 0.f, pxb2 = 0.f;
    if (kh == 0) {
        pxa0 = px0p[0]; pxb0 = px1p[0];
        pxa1 = px0p[1]; pxb1 = px1p[1];
    }
    __syncthreads();

#pragma unroll 1
    for (int t = 0; t < Tsz; ++t) {
        if (kh == 0 && t + 2 < Tsz) {
            pxa2 = px0p[t + 2];
            pxb2 = px1p[t + 2];
        }
        float2 a0 = make_float2(0.f, 0.f), a1 = make_float2(0.f, 0.f);
        const float4* sp0 = (const float4*)(&s_s[0][kh * 64]);
        const float4* sp1 = (const float4*)(&s_s[1][kh * 64]);
#pragma unroll
        for (int i = 0; i < 16; ++i) {
            float4 v0 = sp0[i];
            a0 = ffma2(make_float2(v0.x, v0.y), w1[2 * i],     a0);
            a0 = ffma2(make_float2(v0.z, v0.w), w1[2 * i + 1], a0);
            float4 v1 = sp1[i];
            a1 = ffma2(make_float2(v1.x, v1.y), w1[2 * i],     a1);
            a1 = ffma2(make_float2(v1.z, v1.w), w1[2 * i + 1], a1);
        }
        float p0 = a0.x + a0.y; p0 += __shfl_xor_sync(0xffffffffu, p0, 1);
        float p1 = a1.x + a1.y; p1 += __shfl_xor_sync(0xffffffffu, p1, 1);
        if (kh == 0) { s_y[0][out] = p0 + pxa0; s_y[1][out] = p1 + pxb0; }
        __syncthreads();

        float2 c0 = make_float2(0.f, 0.f), c1 = make_float2(0.f, 0.f);
        const float4* yp0 = (const float4*)(&s_y[0][kh * 64]);
        const float4* yp1 = (const float4*)(&s_y[1][kh * 64]);
#pragma unroll
        for (int i = 0; i < 16; ++i) {
            float4 v0 = yp0[i];
            c0 = ffma2(make_float2(v0.x, v0.y), w2[2 * i],     c0);
            c0 = ffma2(make_float2(v0.z, v0.w), w2[2 * i + 1], c0);
            float4 v1 = yp1[i];
            c1 = ffma2(make_float2(v1.x, v1.y), w2[2 * i],     c1);
            c1 = ffma2(make_float2(v1.z, v1.w), w2[2 * i + 1], c1);
        }
        float q0 = c0.x + c0.y; q0 += __shfl_xor_sync(0xffffffffu, q0, 1);
        float q1 = c1.x + c1.y; q1 += __shfl_xor_sync(0xffffffffu, q1, 1);
        if (kh == 0) {
            float sub0 = fmaxf(q0 + dbv, 0.f);
            float sub1 = fmaxf(q1 + dbv, 0.f);
            so0p[(size_t)t * (NSUB * Bsz * 128)] = sub0;
            so1p[(size_t)t * (NSUB * Bsz * 128)] = sub1;
            s_s[0][out] = rhv * sub0 + rxv * s_s[0][out];
            s_s[1][out] = rhv * sub1 + rxv * s_s[1][out];
        }
        pxa0 = pxa1; pxa1 = pxa2;
        pxb0 = pxb1; pxb1 = pxb2;
        __syncthreads();
    }
}

// Phase 3: h/c chain. 64 CTAs (batch), 384 threads (gate column).
__global__ void __launch_bounds__(384, 1) chain_h_kernel(
    const float* __restrict__ rk,    // (128,384)
    const float* __restrict__ bias,  // (384)
    float* __restrict__ out)         // (64,2048,128)
{
    const int b = blockIdx.x;
    const int g = threadIdx.x;

    __shared__ __align__(16) float s_h[128];
    __shared__ float s_g[384];

    float2 w[64];
#pragma unroll
    for (int i = 0; i < 64; ++i)
        w[i] = make_float2(rk[(2 * i) * 384 + g], rk[(2 * i + 1) * 384 + g]);
    const float bv = bias[g];

    // streaming gate-preact pointer: [b][g][t], t contiguous per thread
    const float* gxp = g_gxpx + ((size_t)b * WCOLS + g) * Tsz;
    const float* op  = g_obuf + b * 128 + g;
    float* outp = out + (size_t)b * (Tsz * 128) + g;

    float c = 0.f;
    if (g < 128) s_h[g] = 0.f;

    float gx0 = gxp[0], gx1 = gxp[1], gx2 = 0.f;
    float o0 = 0.f, o1 = 0.f, o2 = 0.f;
    if (g < 128) { o0 = op[0]; o1 = op[Bsz * 128]; }
    __syncthreads();

#pragma unroll 1
    for (int t = 0; t < Tsz; ++t) {
        if (t + 2 < Tsz) {
            gx2 = gxp[t + 2];
            if (g < 128) o2 = op[(size_t)(t + 2) * (Bsz * 128)];
        }
        float2 acc = make_float2(0.f, 0.f);
        const float4* hp = (const float4*)s_h;
#pragma unroll
        for (int i = 0; i < 32; ++i) {
            float4 v = hp[i];
            acc = ffma2(make_float2(v.x, v.y), w[2 * i],     acc);
            acc = ffma2(make_float2(v.z, v.w), w[2 * i + 1], acc);
        }
        s_g[g] = sigmoidf_(acc.x + acc.y + gx0 + bv);
        __syncthreads();
        if (g < 128) {
            float ig = s_g[g], fg = s_g[g + 128], cg = s_g[g + 256];
            c = fg * c + ig * tanhf(cg);
            float h = o0 * tanhf(c);
            s_h[g] = h;
            outp[(size_t)t * 128] = h;
        }
        gx0 = gx1; gx1 = gx2;
        o0 = o1;  o1 = o2;
        __syncthreads();
    }
}

extern "C" void kernel_launch(void* const* d_in, const int* in_sizes, int n_in,
                              void* d_out, int out_size) {
    const float* x    = (const float*)d_in[0];
    const float* kern = (const float*)d_in[1];
    const float* rk   = (const float*)d_in[2];
    const float* bias = (const float*)d_in[3];
    const float* skx  = (const float*)d_in[4];
    const float* skh  = (const float*)d_in[5];
    const float* stk  = (const float*)d_in[6];
    const float* dw   = (const float*)d_in[7];
    const float* db   = (const float*)d_in[8];
    const float* aggw = (const float*)d_in[9];
    const float* aggb = (const float*)d_in[10];
    float* out = (float*)d_out;

    prep_wcat_kernel<<<(Dsz * WCOLS + 255) / 256, 256>>>(kern, skx);
    gemm_phase0_kernel<<<dim3((Bsz * Tsz) / 128, WCOLS / 128), 256>>>(x);
    chain_s_kernel<<<NSUB * 32, 256>>>(skh, dw, db, stk);
    gemm_phase2_kernel<<<dim3((Tsz * Bsz) / 128, 1), 256>>>(aggw, aggb);
    chain_h_kernel<<<Bsz, 384>>>(rk, bias, out);
}

// round 17
// speedup vs baseline: 1.2822x; 1.2822x over previous
#include <cuda_runtime.h>
#include <cuda_bf16.h>
#include <math.h>

#define Bsz 64
#define Tsz 2048
#define Dsz 128
#define NSUB 3
#define WCOLS 768

__device__ float g_Wcat[Dsz * WCOLS];                 // [d][0:384]=kernel, [d][384+n*128+o']=skx@dw
__device__ float g_Wc[NSUB * 128 * 128];              // Wc[n][k][o'] = skh[n]@dw[n]
// TRANSPOSED activations: [b][g][t] (t contiguous)
__device__ float g_gxpx[(size_t)Bsz * WCOLS * Tsz];
__device__ float g_subo[(size_t)Tsz * NSUB * Bsz * 128];  // [t][n][b][o]
__device__ float g_obuf[(size_t)Tsz * Bsz * 128];         // [t][b][u]

__device__ __forceinline__ float2 ffma2(float2 a, float2 b, float2 c) {
    union U { float2 f2; unsigned long long u; };
    U ua, ub, uc, ud;
    ua.f2 = a; ub.f2 = b; uc.f2 = c;
    asm("fma.rn.f32x2 %0, %1, %2, %3;"
        : "=l"(ud.u) : "l"(ua.u), "l"(ub.u), "l"(uc.u));
    return ud.f2;
}

__device__ __forceinline__ float sigmoidf_(float x) {
    return 1.0f / (1.0f + __expf(-x));
}

// ---------------------------------------------------------------------------
// Prep
// ---------------------------------------------------------------------------
__global__ void prep_copy_kernel(const float* __restrict__ kern) {
    int idx = blockIdx.x * 256 + threadIdx.x;
    if (idx >= Dsz * 384) return;
    int d = idx / 384, g = idx - d * 384;
    g_Wcat[d * WCOLS + g] = kern[idx];
}

// grid (3, 256): r<128 -> Wc row (skh@dw); r>=128 -> Wcat fused cols (skx@dw)
__global__ void prep_fuse_kernel(const float* __restrict__ skh,
                                 const float* __restrict__ skx,
                                 const float* __restrict__ dw) {
    int n = blockIdx.x;
    int r = blockIdx.y;
    int o = threadIdx.x;
    const float* A = (r < 128) ? (skh + n * 16384 + r * 128)
                               : (skx + n * 16384 + (r - 128) * 128);
    const float* Dn = dw + n * 16384;
    float acc = 0.f;
#pragma unroll 8
    for (int i = 0; i < 128; ++i)
        acc = fmaf(A[i], Dn[i * 128 + o], acc);
    if (r < 128) g_Wc[n * 16384 + r * 128 + o] = acc;
    else         g_Wcat[(size_t)(r - 128) * WCOLS + 384 + n * 128 + o] = acc;
}

// ---------------------------------------------------------------------------
// Tiled fp32 GEMM: 128x128 tile, BK=32, 256 threads, 8x8 micro via f32x2.
// TRANS=true: write C transposed as [b][g][t] (phase0); else row-major.
// ---------------------------------------------------------------------------
template <bool TRANS>
__device__ __forceinline__ void gemm_body(
    const float* __restrict__ A, const float* __restrict__ B,
    float* __restrict__ C, int N, int K,
    const float* __restrict__ bias, bool act)
{
    __shared__ __align__(16) float As[32][132];
    __shared__ __align__(16) float Bs[32][128];
    const int tid = threadIdx.x;
    const int tx = tid & 15, ty = tid >> 4;
    const int m0 = blockIdx.x * 128, n0 = blockIdx.y * 128;

    float2 acc[8][4];
#pragma unroll
    for (int i = 0; i < 8; ++i)
#pragma unroll
        for (int j = 0; j < 4; ++j) acc[i][j] = make_float2(0.f, 0.f);

    const int aR = tid >> 3, aC = (tid & 7) * 4;
    const int bR = tid >> 5, bC = (tid & 31) * 4;

    for (int k0 = 0; k0 < K; k0 += 32) {
#pragma unroll
        for (int r = 0; r < 4; ++r) {
            float4 v = *(const float4*)(A + (size_t)(m0 + r * 32 + aR) * K + (k0 + aC));
            As[aC + 0][r * 32 + aR] = v.x;
            As[aC + 1][r * 32 + aR] = v.y;
            As[aC + 2][r * 32 + aR] = v.z;
            As[aC + 3][r * 32 + aR] = v.w;
        }
#pragma unroll
        for (int r = 0; r < 4; ++r)
            *(float4*)&Bs[r * 8 + bR][bC] =
                *(const float4*)(B + (size_t)(k0 + r * 8 + bR) * N + (n0 + bC));
        __syncthreads();
#pragma unroll
        for (int kk = 0; kk < 32; ++kk) {
            float4 a0 = *(const float4*)&As[kk][ty * 8];
            float4 a1 = *(const float4*)&As[kk][ty * 8 + 4];
            float4 b0 = *(const float4*)&Bs[kk][tx * 8];
            float4 b1 = *(const float4*)&Bs[kk][tx * 8 + 4];
            float2 bb[4] = { make_float2(b0.x, b0.y), make_float2(b0.z, b0.w),
                             make_float2(b1.x, b1.y), make_float2(b1.z, b1.w) };
            float av[8] = { a0.x, a0.y, a0.z, a0.w, a1.x, a1.y, a1.z, a1.w };
#pragma unroll
            for (int i = 0; i < 8; ++i) {
                float2 ad = make_float2(av[i], av[i]);
#pragma unroll
                for (int j = 0; j < 4; ++j)
                    acc[i][j] = ffma2(ad, bb[j], acc[i][j]);
            }
        }
        __syncthreads();
    }

    if (TRANS) {
        const int bb_ = m0 / Tsz;
        const int t0 = m0 - bb_ * Tsz;
        float* base = C + (size_t)bb_ * WCOLS * Tsz + t0 + ty * 8;
#pragma unroll
        for (int j = 0; j < 8; ++j) {
            const int g = n0 + tx * 8 + j;
            float o0 = (j & 1) ? acc[0][j >> 1].y : acc[0][j >> 1].x;
            float o1 = (j & 1) ? acc[1][j >> 1].y : acc[1][j >> 1].x;
            float o2 = (j & 1) ? acc[2][j >> 1].y : acc[2][j >> 1].x;
            float o3 = (j & 1) ? acc[3][j >> 1].y : acc[3][j >> 1].x;
            float o4 = (j & 1) ? acc[4][j >> 1].y : acc[4][j >> 1].x;
            float o5 = (j & 1) ? acc[5][j >> 1].y : acc[5][j >> 1].x;
            float o6 = (j & 1) ? acc[6][j >> 1].y : acc[6][j >> 1].x;
            float o7 = (j & 1) ? acc[7][j >> 1].y : acc[7][j >> 1].x;
            *(float4*)(base + (size_t)g * Tsz)     = make_float4(o0, o1, o2, o3);
            *(float4*)(base + (size_t)g * Tsz + 4) = make_float4(o4, o5, o6, o7);
        }
    } else {
        float bvals[8];
#pragma unroll
        for (int j = 0; j < 8; ++j)
            bvals[j] = bias ? bias[n0 + tx * 8 + j] : 0.f;
#pragma unroll
        for (int i = 0; i < 8; ++i) {
            int m = m0 + ty * 8 + i;
            float o[8];
#pragma unroll
            for (int j = 0; j < 4; ++j) {
                o[2 * j + 0] = acc[i][j].x + bvals[2 * j + 0];
                o[2 * j + 1] = acc[i][j].y + bvals[2 * j + 1];
            }
            if (act) {
#pragma unroll
                for (int j = 0; j < 8; ++j) o[j] = sigmoidf_(o[j]);
            }
            *(float4*)&C[(size_t)m * N + n0 + tx * 8]     = make_float4(o[0], o[1], o[2], o[3]);
            *(float4*)&C[(size_t)m * N + n0 + tx * 8 + 4] = make_float4(o[4], o[5], o[6], o[7]);
        }
    }
}

__global__ void __launch_bounds__(256) gemm_phase0_kernel(const float* __restrict__ x) {
    gemm_body<true>(x, g_Wcat, g_gxpx, WCOLS, Dsz, nullptr, false);
}

__global__ void __launch_bounds__(256) gemm_phase2_kernel(const float* __restrict__ aggw,
                                                          const float* __restrict__ aggb) {
    gemm_body<false>(g_subo, aggw, g_obuf, 128, NSUB * 128, aggb, true);
}

// ---------------------------------------------------------------------------
// Phase 1 (FUSED): sub_o = relu(pxd_t + s@Wc + db);  s' = rh*sub_o + rx*s
// One matvec + ONE barrier per step (double-buffered s).
// blk: n = blk/32, batch pair b0 = (blk%32)*2. 256 thr: out=tid>>1, kh=tid&1.
// Lane kh owns batch row b0+kh for prefetch/epilogue.
// ---------------------------------------------------------------------------
__global__ void __launch_bounds__(256, 1) chain_s_kernel(
    const float* __restrict__ db,    // (3,128)
    const float* __restrict__ stk)   // (3,256) [rh|rx]
{
    const int n  = blockIdx.x >> 5;
    const int b0 = (blockIdx.x & 31) * 2;
    const int tid = threadIdx.x;
    const int out = tid >> 1, kh = tid & 1;

    __shared__ __align__(16) float s_s[2][2][128];   // [buf][row][u]

    const float* wc_n = g_Wc + n * 16384;
    float2 w2[32];
#pragma unroll
    for (int i = 0; i < 32; ++i) {
        int k = kh * 64 + 2 * i;
        w2[i] = make_float2(wc_n[k * 128 + out], wc_n[(k + 1) * 128 + out]);
    }
    const float dbv = db[n * 128 + out];
    const float rhv = stk[n * 256 + out];
    const float rxv = stk[n * 256 + 128 + out];

    const int gcol = 384 + n * 128 + out;
    const int brow = b0 + kh;
    const float* pxp = g_gxpx + ((size_t)brow * WCOLS + gcol) * Tsz;
    float* sop = g_subo + n * (Bsz * 128) + brow * 128 + out;

    if (tid < 128) {
        s_s[0][0][tid] = 0.f; s_s[0][1][tid] = 0.f;
        s_s[1][0][tid] = 0.f; s_s[1][1][tid] = 0.f;
    }

    float px0 = pxp[0], px1 = pxp[1], px2 = 0.f;
    __syncthreads();

    int p = 0;
#pragma unroll 1
    for (int t = 0; t < Tsz; ++t) {
        if (t + 2 < Tsz) px2 = pxp[t + 2];
        float2 a0 = make_float2(0.f, 0.f), a1 = make_float2(0.f, 0.f);
        const float4* sp0 = (const float4*)&s_s[p][0][kh * 64];
        const float4* sp1 = (const float4*)&s_s[p][1][kh * 64];
#pragma unroll
        for (int i = 0; i < 16; ++i) {
            float4 v0 = sp0[i];
            a0 = ffma2(make_float2(v0.x, v0.y), w2[2 * i],     a0);
            a0 = ffma2(make_float2(v0.z, v0.w), w2[2 * i + 1], a0);
            float4 v1 = sp1[i];
            a1 = ffma2(make_float2(v1.x, v1.y), w2[2 * i],     a1);
            a1 = ffma2(make_float2(v1.z, v1.w), w2[2 * i + 1], a1);
        }
        float q0 = a0.x + a0.y; q0 += __shfl_xor_sync(0xffffffffu, q0, 1);
        float q1 = a1.x + a1.y; q1 += __shfl_xor_sync(0xffffffffu, q1, 1);
        float q = kh ? q1 : q0;
        float sub = fmaxf(q + px0 + dbv, 0.f);
        sop[(size_t)t * (NSUB * Bsz * 128)] = sub;
        float sold = s_s[p][kh][out];
        s_s[p ^ 1][kh][out] = rhv * sub + rxv * sold;
        px0 = px1; px1 = px2;
        __syncthreads();
        p ^= 1;
    }
}

// ---------------------------------------------------------------------------
// Phase 3: h/c chain. 64 CTAs (batch), 384 threads (gate column).
// ---------------------------------------------------------------------------
__global__ void __launch_bounds__(384, 1) chain_h_kernel(
    const float* __restrict__ rk,    // (128,384)
    const float* __restrict__ bias,  // (384)
    float* __restrict__ out)         // (64,2048,128)
{
    const int b = blockIdx.x;
    const int g = threadIdx.x;

    __shared__ __align__(16) float s_h[128];
    __shared__ float s_g[384];

    float2 w[64];
#pragma unroll
    for (int i = 0; i < 64; ++i)
        w[i] = make_float2(rk[(2 * i) * 384 + g], rk[(2 * i + 1) * 384 + g]);
    const float bv = bias[g];

    const float* gxp = g_gxpx + ((size_t)b * WCOLS + g) * Tsz;
    const float* op  = g_obuf + b * 128 + g;
    float* outp = out + (size_t)b * (Tsz * 128) + g;

    float c = 0.f;
    if (g < 128) s_h[g] = 0.f;

    float gx0 = gxp[0], gx1 = gxp[1], gx2 = 0.f;
    float o0 = 0.f, o1 = 0.f, o2 = 0.f;
    if (g < 128) { o0 = op[0]; o1 = op[Bsz * 128]; }
    __syncthreads();

#pragma unroll 1
    for (int t = 0; t < Tsz; ++t) {
        if (t + 2 < Tsz) {
            gx2 = gxp[t + 2];
            if (g < 128) o2 = op[(size_t)(t + 2) * (Bsz * 128)];
        }
        float2 acc = make_float2(0.f, 0.f);
        const float4* hp = (const float4*)s_h;
#pragma unroll
        for (int i = 0; i < 32; ++i) {
            float4 v = hp[i];
            acc = ffma2(make_float2(v.x, v.y), w[2 * i],     acc);
            acc = ffma2(make_float2(v.z, v.w), w[2 * i + 1], acc);
        }
        s_g[g] = sigmoidf_(acc.x + acc.y + gx0 + bv);
        __syncthreads();
        if (g < 128) {
            float ig = s_g[g], fg = s_g[g + 128], cg = s_g[g + 256];
            c = fg * c + ig * tanhf(cg);
            float h = o0 * tanhf(c);
            s_h[g] = h;
            outp[(size_t)t * 128] = h;
        }
        gx0 = gx1; gx1 = gx2;
        o0 = o1;  o1 = o2;
        __syncthreads();
    }
}

extern "C" void kernel_launch(void* const* d_in, const int* in_sizes, int n_in,
                              void* d_out, int out_size) {
    const float* x    = (const float*)d_in[0];
    const float* kern = (const float*)d_in[1];
    const float* rk   = (const float*)d_in[2];
    const float* bias = (const float*)d_in[3];
    const float* skx  = (const float*)d_in[4];
    const float* skh  = (const float*)d_in[5];
    const float* stk  = (const float*)d_in[6];
    const float* dw   = (const float*)d_in[7];
    const float* db   = (const float*)d_in[8];
    const float* aggw = (const float*)d_in[9];
    const float* aggb = (const float*)d_in[10];
    float* out = (float*)d_out;

    prep_copy_kernel<<<(Dsz * 384 + 255) / 256, 256>>>(kern);
    prep_fuse_kernel<<<dim3(NSUB, 256), 128>>>(skh, skx, dw);
    gemm_phase0_kernel<<<dim3((Bsz * Tsz) / 128, WCOLS / 128), 256>>>(x);
    chain_s_kernel<<<NSUB * 32, 256>>>(db, stk);
    gemm_phase2_kernel<<<dim3((Tsz * Bsz) / 128, 1), 256>>>(aggw, aggb);
    chain_h_kernel<<<Bsz, 384>>>(rk, bias, out);
}